// round 15
// baseline (speedup 1.0000x reference)
#include <cuda_runtime.h>
#include <cuda_fp16.h>
#include <stdint.h>

#define D 128
#define DV 32
#define MAXN 50048
#define MAXE 1600000

// Zero-initialized at module load. Invariant: g_deg, g_cnt, g_done are zero at
// entry to kernel_launch and restored before it finishes
// (prep_scan zeroes deg + done; the final k_agg zeroes cnt).
__device__ int      g_deg[MAXN];
__device__ int      g_cnt[MAXN];
__device__ int      g_done;
__device__ int      g_adjs[MAXE];       // dst-sorted src ids (weights folded into t')
__device__ int      g_start[MAXN + 1];  // CSR offsets by dst
__device__ float    g_dis[MAXN];
__device__ __half   g_th[MAXN * D];     // layer-1 t' = dis*(x@W1), fp16
__device__ __half   g_th2[MAXN * D];    // layer-2 t' = dis*(h@W2), fp16
__device__ unsigned g_w1p[D * D];       // W1, tf32 bits, lane-major fragment pack
__device__ unsigned g_w2p[D * D];       // W2, tf32 bits, lane-major fragment pack

__device__ __forceinline__ unsigned f2tf32(float f) {
    unsigned u;
    asm("cvt.rna.tf32.f32 %0, %1;" : "=r"(u) : "f"(f));
    return u;
}

// Lane-major fragment pack (see consumer in the GEMM):
//   word i = (((kk4*4 + wn)*4 + ks)*2 + jj)*128 + lane*4 + c
__device__ __forceinline__ void pack_w(unsigned* dst, const float* __restrict__ W, int i) {
    int c    = i & 3;
    int lane = (i >> 2) & 31;
    int jj   = (i >> 7) & 1;
    int ks   = (i >> 8) & 3;
    int wn   = (i >> 10) & 3;
    int kk4  = i >> 12;
    int j  = jj * 4 + c;
    int nt = j >> 1;
    int b  = j & 1;
    int t  = lane & 3;
    int g  = lane >> 2;
    int k = kk4 * 32 + ks * 8 + t + b * 4;
    int n = wn * 32 + nt * 8 + g;
    dst[i] = f2tf32(W[k * D + n]);
}

// ---------------------------------------------------------------------------
// Per-block dtype detect: int64 little-endian values < 2^32 -> odd 32-bit
// words all zero over 128 samples.
// ---------------------------------------------------------------------------
__device__ __forceinline__ int detect_is64(const unsigned* p, int* s_flag) {
    if (threadIdx.x == 0) *s_flag = 0;
    __syncthreads();
    if (threadIdx.x < 64) {
        unsigned nz = p[2 * threadIdx.x + 1] | p[2 * threadIdx.x + 129];
        if (nz) atomicOr(s_flag, 1);
    }
    __syncthreads();
    return *s_flag ? 0 : 1;
}

// ---------------------------------------------------------------------------
// FUSED prep + scan (last-block-done).
// ---------------------------------------------------------------------------
__global__ void k_prep_scan(const void* p, int E, int N,
                            const float* __restrict__ W1, const float* __restrict__ W2) {
    __shared__ int s_flag;
    __shared__ int s_last;
    int is64 = detect_is64((const unsigned*)p, &s_flag);
    int gt = blockIdx.x * blockDim.x + threadIdx.x;

    if (gt < D * D)          pack_w(g_w1p, W1, gt);
    else if (gt < 2 * D * D) pack_w(g_w2p, W2, gt - D * D);

    if (gt < E) {
        int r, c;
        if (is64) {
            const long long* q = (const long long*)p;
            r = (int)q[gt];
            c = (int)q[(long long)E + gt];
        } else {
            const int* q = (const int*)p;
            r = q[gt];
            c = q[E + gt];
        }
        atomicAdd(&g_deg[r], 1);
        atomicAdd(&g_cnt[c], 1);
    }

    __syncthreads();
    if (threadIdx.x == 0) {
        __threadfence();
        s_last = (atomicAdd(&g_done, 1) == (int)gridDim.x - 1);
    }
    __syncthreads();
    if (!s_last) return;
    __threadfence();

    __shared__ int warpBase[8];
    const int tid  = threadIdx.x;
    const int lane = tid & 31;
    const int wid  = tid >> 5;
    const int per  = (N + 255) >> 8;
    const int base = tid * per;

    int s = 0;
    {
        int i = 0;
        for (; i + 4 <= per; i += 4) {
            int i0 = base + i;
            int c0 = (i0     < N) ? g_cnt[i0]     : 0;
            int c1 = (i0 + 1 < N) ? g_cnt[i0 + 1] : 0;
            int c2 = (i0 + 2 < N) ? g_cnt[i0 + 2] : 0;
            int c3 = (i0 + 3 < N) ? g_cnt[i0 + 3] : 0;
            s += (c0 + c1) + (c2 + c3);
        }
        for (; i < per; i++) {
            int i0 = base + i;
            if (i0 < N) s += g_cnt[i0];
        }
    }

    int incl = s;
    #pragma unroll
    for (int off = 1; off < 32; off <<= 1) {
        int v = __shfl_up_sync(0xffffffffu, incl, off);
        if (lane >= off) incl += v;
    }
    if (lane == 31) warpBase[wid] = incl;
    __syncthreads();
    if (wid == 0 && lane < 8) {
        int wv = warpBase[lane];
        int wi = wv;
        #pragma unroll
        for (int off = 1; off < 8; off <<= 1) {
            int v = __shfl_up_sync(0xffu, wi, off);
            if (lane >= off) wi += v;
        }
        warpBase[lane] = wi - wv;
    }
    __syncthreads();
    int run = warpBase[wid] + (incl - s);

    {
        int i = 0;
        for (; i + 4 <= per; i += 4) {
            int i0 = base + i;
            int c0 = (i0     < N) ? g_cnt[i0]     : 0;
            int c1 = (i0 + 1 < N) ? g_cnt[i0 + 1] : 0;
            int c2 = (i0 + 2 < N) ? g_cnt[i0 + 2] : 0;
            int c3 = (i0 + 3 < N) ? g_cnt[i0 + 3] : 0;
            int d0 = (i0     < N) ? g_deg[i0]     : 0;
            int d1 = (i0 + 1 < N) ? g_deg[i0 + 1] : 0;
            int d2 = (i0 + 2 < N) ? g_deg[i0 + 2] : 0;
            int d3 = (i0 + 3 < N) ? g_deg[i0 + 3] : 0;
            if (i0 < N) {
                g_start[i0] = run;  g_cnt[i0] = 0;  g_deg[i0] = 0;
                g_dis[i0] = rsqrtf((float)(d0 + 1));
            }
            if (i0 + 1 < N) {
                g_start[i0 + 1] = run + c0;  g_cnt[i0 + 1] = 0;  g_deg[i0 + 1] = 0;
                g_dis[i0 + 1] = rsqrtf((float)(d1 + 1));
            }
            if (i0 + 2 < N) {
                g_start[i0 + 2] = run + c0 + c1;  g_cnt[i0 + 2] = 0;  g_deg[i0 + 2] = 0;
                g_dis[i0 + 2] = rsqrtf((float)(d2 + 1));
            }
            if (i0 + 3 < N) {
                g_start[i0 + 3] = run + c0 + c1 + c2;  g_cnt[i0 + 3] = 0;  g_deg[i0 + 3] = 0;
                g_dis[i0 + 3] = rsqrtf((float)(d3 + 1));
            }
            run += (c0 + c1) + (c2 + c3);
        }
        for (; i < per; i++) {
            int i0 = base + i;
            if (i0 < N) {
                int c = g_cnt[i0];
                g_start[i0] = run;  run += c;
                g_cnt[i0] = 0;
                g_dis[i0] = rsqrtf((float)(g_deg[i0] + 1));
                g_deg[i0] = 0;
            }
        }
    }
    if (tid == 0) {
        g_start[N] = E;
        g_done = 0;
    }
}

// ---------------------------------------------------------------------------
// FUSED: blocks [0, gemmBlocks) run GEMM-1 (tf32, dis[row]*(x@W1) -> g_th);
//        blocks [gemmBlocks, ...) scatter edge src ids into the adjacency.
// ---------------------------------------------------------------------------
__global__ void __launch_bounds__(256, 3)
k_gemm_scatter(const float* __restrict__ A, const unsigned* __restrict__ Wp,
               __half* __restrict__ C, int N,
               const void* p, int E, int gemmBlocks) {
    __shared__ unsigned As[64][36];

    if (blockIdx.x >= gemmBlocks) {
        int is64 = detect_is64((const unsigned*)p, (int*)&As[0][0]);
        int e = (blockIdx.x - gemmBlocks) * blockDim.x + threadIdx.x;
        if (e >= E) return;
        int r, c;
        if (is64) {
            const long long* q = (const long long*)p;
            r = (int)q[e];
            c = (int)q[(long long)E + e];
        } else {
            const int* q = (const int*)p;
            r = q[e];
            c = q[E + e];
        }
        int pos = g_start[c] + atomicAdd(&g_cnt[c], 1);
        g_adjs[pos] = r;
        return;
    }

    const int tid  = threadIdx.x;
    const int wid  = tid >> 5;
    const int lane = tid & 31;
    const int g    = lane >> 2;
    const int t    = lane & 3;
    const int wm   = wid >> 2;
    const int wn   = wid & 3;
    const int row0 = blockIdx.x * 64;

    float acc[2][4][4];
    #pragma unroll
    for (int mt = 0; mt < 2; mt++)
        #pragma unroll
        for (int nt = 0; nt < 4; nt++)
            #pragma unroll
            for (int c = 0; c < 4; c++) acc[mt][nt][c] = 0.f;

    for (int kk4 = 0; kk4 < 4; kk4++) {
        const int kk = kk4 * 32;
        #pragma unroll
        for (int it = 0; it < 2; it++) {
            int idx = tid + it * 256;
            int m  = idx >> 3;
            int k4 = idx & 7;
            float4 v = make_float4(0.f, 0.f, 0.f, 0.f);
            int gr = row0 + m;
            if (gr < N) v = *(const float4*)(A + (long)gr * D + kk + k4 * 4);
            As[m][k4 * 4 + 0] = f2tf32(v.x);
            As[m][k4 * 4 + 1] = f2tf32(v.y);
            As[m][k4 * 4 + 2] = f2tf32(v.z);
            As[m][k4 * 4 + 3] = f2tf32(v.w);
        }
        __syncthreads();

        const unsigned* wsl = Wp + ((kk4 * 4 + wn) * 4) * 256 + lane * 4;
        #pragma unroll
        for (int ks = 0; ks < 4; ks++) {
            uint4 u0 = __ldg((const uint4*)(wsl + ks * 256));
            uint4 u1 = __ldg((const uint4*)(wsl + ks * 256 + 128));
            unsigned bf[4][2] = {{u0.x, u0.y}, {u0.z, u0.w},
                                 {u1.x, u1.y}, {u1.z, u1.w}};
            #pragma unroll
            for (int mt = 0; mt < 2; mt++) {
                int mb = wm * 32 + mt * 16;
                unsigned a0 = As[mb + g    ][ks * 8 + t    ];
                unsigned a1 = As[mb + g + 8][ks * 8 + t    ];
                unsigned a2 = As[mb + g    ][ks * 8 + t + 4];
                unsigned a3 = As[mb + g + 8][ks * 8 + t + 4];
                #pragma unroll
                for (int nt = 0; nt < 4; nt++) {
                    asm volatile(
                        "mma.sync.aligned.m16n8k8.row.col.f32.tf32.tf32.f32 "
                        "{%0,%1,%2,%3}, {%4,%5,%6,%7}, {%8,%9}, {%0,%1,%2,%3};"
                        : "+f"(acc[mt][nt][0]), "+f"(acc[mt][nt][1]),
                          "+f"(acc[mt][nt][2]), "+f"(acc[mt][nt][3])
                        : "r"(a0), "r"(a1), "r"(a2), "r"(a3),
                          "r"(bf[nt][0]), "r"(bf[nt][1]));
                }
            }
        }
        __syncthreads();
    }

    #pragma unroll
    for (int mt = 0; mt < 2; mt++) {
        int r0 = row0 + wm * 32 + mt * 16 + g;
        int r1 = r0 + 8;
        float d0 = (r0 < N) ? g_dis[r0] : 0.f;
        float d1 = (r1 < N) ? g_dis[r1] : 0.f;
        #pragma unroll
        for (int nt = 0; nt < 4; nt++) {
            int n = wn * 32 + nt * 8 + 2 * t;
            if (r0 < N)
                *(__half2*)(C + (long)r0 * D + n) =
                    __floats2half2_rn(d0 * acc[mt][nt][0], d0 * acc[mt][nt][1]);
            if (r1 < N)
                *(__half2*)(C + (long)r1 * D + n) =
                    __floats2half2_rn(d1 * acc[mt][nt][2], d1 * acc[mt][nt][3]);
        }
    }
}

// ---------------------------------------------------------------------------
// FUSED agg-1 + GEMM-2: each block owns 64 dst nodes. Phase 1: 8 warps
// aggregate 8 nodes each (fp16 tree sum of t1' neighbors + self, dis, bias,
// ReLU) and write the h tile straight into the tf32 smem slabs. Phase 2: the
// proven mma loop consumes the slabs (zero global A traffic, zero per-slab
// syncs) and writes t2' = dis*(h@W2) to a SEPARATE buffer (no hazard).
// Slab stride 2312 words: slabs offset by 8 banks -> lane 0/8/16/24 stores
// hit distinct bank groups.
// ---------------------------------------------------------------------------
__global__ void __launch_bounds__(256, 3)
k_agg_gemm(const uint2* __restrict__ src, const float4* __restrict__ bias4,
           const unsigned* __restrict__ Wp, __half* __restrict__ C, int N) {
    __shared__ unsigned As4[4 * 2312];   // 4 slabs, [m][36] each, +8-word skew

    const int tid  = threadIdx.x;
    const int wid  = tid >> 5;
    const int lane = tid & 31;
    const int g    = lane >> 2;
    const int t    = lane & 3;
    const int wm   = wid >> 2;
    const int wn   = wid & 3;
    const int row0 = blockIdx.x * 64;

    // ---- Phase 1: aggregate 8 nodes per warp into the slabs ----
    {
        const int slab = lane >> 3;             // 0..3
        const int off  = (lane & 7) * 4;        // 0..28, this lane's 4 cols in-slab
        float4 bv = __ldg(&bias4[lane]);
        #pragma unroll 1
        for (int j = 0; j < 8; j++) {
            int m = wid * 8 + j;
            int w = row0 + m;
            float4 o = make_float4(0.f, 0.f, 0.f, 0.f);
            if (w < N) {
                int i = g_start[w];
                const int end = g_start[w + 1];
                float4 a0 = make_float4(0.f, 0.f, 0.f, 0.f);
                while ((i & 3) && i < end) {
                    uint2 p = __ldg(&src[__ldg(&g_adjs[i]) * 32 + lane]);
                    float2 fa = __half22float2(*(__half2*)&p.x);
                    float2 fb = __half22float2(*(__half2*)&p.y);
                    a0.x += fa.x; a0.y += fa.y; a0.z += fb.x; a0.w += fb.y;
                    i++;
                }
                for (; i + 4 <= end; i += 4) {
                    int4 e = __ldg((const int4*)&g_adjs[i]);
                    uint2 p0 = __ldg(&src[e.x * 32 + lane]);
                    uint2 p1 = __ldg(&src[e.y * 32 + lane]);
                    uint2 p2 = __ldg(&src[e.z * 32 + lane]);
                    uint2 p3 = __ldg(&src[e.w * 32 + lane]);
                    __half2 q0a = __hadd2(*(__half2*)&p0.x, *(__half2*)&p1.x);
                    __half2 q0b = __hadd2(*(__half2*)&p0.y, *(__half2*)&p1.y);
                    __half2 q1a = __hadd2(*(__half2*)&p2.x, *(__half2*)&p3.x);
                    __half2 q1b = __hadd2(*(__half2*)&p2.y, *(__half2*)&p3.y);
                    __half2 ra  = __hadd2(q0a, q1a);
                    __half2 rb  = __hadd2(q0b, q1b);
                    float2 f;
                    f = __half22float2(ra); a0.x += f.x; a0.y += f.y;
                    f = __half22float2(rb); a0.z += f.x; a0.w += f.y;
                }
                for (; i < end; i++) {
                    uint2 p = __ldg(&src[__ldg(&g_adjs[i]) * 32 + lane]);
                    float2 fa = __half22float2(*(__half2*)&p.x);
                    float2 fb = __half22float2(*(__half2*)&p.y);
                    a0.x += fa.x; a0.y += fa.y; a0.z += fb.x; a0.w += fb.y;
                }
                float di = g_dis[w];
                uint2 ps = __ldg(&src[w * 32 + lane]);
                float2 s0 = __half22float2(*(__half2*)&ps.x);
                float2 s1 = __half22float2(*(__half2*)&ps.y);
                o.x = fmaxf(di * (a0.x + s0.x) + bv.x, 0.f);
                o.y = fmaxf(di * (a0.y + s0.y) + bv.y, 0.f);
                o.z = fmaxf(di * (a0.z + s1.x) + bv.z, 0.f);
                o.w = fmaxf(di * (a0.w + s1.y) + bv.w, 0.f);
            }
            unsigned* dst4 = &As4[slab * 2312 + m * 36 + off];
            dst4[0] = f2tf32(o.x);
            dst4[1] = f2tf32(o.y);
            dst4[2] = f2tf32(o.z);
            dst4[3] = f2tf32(o.w);
        }
    }
    __syncthreads();

    // ---- Phase 2: GEMM from the slabs ----
    float acc[2][4][4];
    #pragma unroll
    for (int mt = 0; mt < 2; mt++)
        #pragma unroll
        for (int nt = 0; nt < 4; nt++)
            #pragma unroll
            for (int c = 0; c < 4; c++) acc[mt][nt][c] = 0.f;

    #pragma unroll 1
    for (int kk4 = 0; kk4 < 4; kk4++) {
        const unsigned* slabp = &As4[kk4 * 2312];
        const unsigned* wsl = Wp + ((kk4 * 4 + wn) * 4) * 256 + lane * 4;
        #pragma unroll
        for (int ks = 0; ks < 4; ks++) {
            uint4 u0 = __ldg((const uint4*)(wsl + ks * 256));
            uint4 u1 = __ldg((const uint4*)(wsl + ks * 256 + 128));
            unsigned bf[4][2] = {{u0.x, u0.y}, {u0.z, u0.w},
                                 {u1.x, u1.y}, {u1.z, u1.w}};
            #pragma unroll
            for (int mt = 0; mt < 2; mt++) {
                int mb = wm * 32 + mt * 16;
                unsigned a0 = slabp[(mb + g    ) * 36 + ks * 8 + t    ];
                unsigned a1 = slabp[(mb + g + 8) * 36 + ks * 8 + t    ];
                unsigned a2 = slabp[(mb + g    ) * 36 + ks * 8 + t + 4];
                unsigned a3 = slabp[(mb + g + 8) * 36 + ks * 8 + t + 4];
                #pragma unroll
                for (int nt = 0; nt < 4; nt++) {
                    asm volatile(
                        "mma.sync.aligned.m16n8k8.row.col.f32.tf32.tf32.f32 "
                        "{%0,%1,%2,%3}, {%4,%5,%6,%7}, {%8,%9}, {%0,%1,%2,%3};"
                        : "+f"(acc[mt][nt][0]), "+f"(acc[mt][nt][1]),
                          "+f"(acc[mt][nt][2]), "+f"(acc[mt][nt][3])
                        : "r"(a0), "r"(a1), "r"(a2), "r"(a3),
                          "r"(bf[nt][0]), "r"(bf[nt][1]));
                }
            }
        }
    }

    #pragma unroll
    for (int mt = 0; mt < 2; mt++) {
        int r0 = row0 + wm * 32 + mt * 16 + g;
        int r1 = r0 + 8;
        float d0 = (r0 < N) ? g_dis[r0] : 0.f;
        float d1 = (r1 < N) ? g_dis[r1] : 0.f;
        #pragma unroll
        for (int nt = 0; nt < 4; nt++) {
            int n = wn * 32 + nt * 8 + 2 * t;
            if (r0 < N)
                *(__half2*)(C + (long)r0 * D + n) =
                    __floats2half2_rn(d0 * acc[mt][nt][0], d0 * acc[mt][nt][1]);
            if (r1 < N)
                *(__half2*)(C + (long)r1 * D + n) =
                    __floats2half2_rn(d1 * acc[mt][nt][2], d1 * acc[mt][nt][3]);
        }
    }
}

// ---------------------------------------------------------------------------
// Final aggregation (layer 2): fp16 tree sum + bias, fp32 out; zeroes g_cnt.
// ---------------------------------------------------------------------------
__global__ void __launch_bounds__(256)
k_agg_out(const uint2* __restrict__ src, const float4* __restrict__ bias4,
          float4* __restrict__ dst, int N) {
    int idx = blockIdx.x * blockDim.x + threadIdx.x;
    if (idx < MAXN) g_cnt[idx] = 0;   // restore invariant
    int w = idx >> 5;
    if (w >= N) return;
    const int lane = threadIdx.x & 31;
    int i = g_start[w];
    const int end = g_start[w + 1];

    float4 a0 = make_float4(0.f, 0.f, 0.f, 0.f);

    while ((i & 3) && i < end) {
        uint2 p = __ldg(&src[__ldg(&g_adjs[i]) * 32 + lane]);
        float2 fa = __half22float2(*(__half2*)&p.x);
        float2 fb = __half22float2(*(__half2*)&p.y);
        a0.x += fa.x; a0.y += fa.y; a0.z += fb.x; a0.w += fb.y;
        i++;
    }
    for (; i + 4 <= end; i += 4) {
        int4 e = __ldg((const int4*)&g_adjs[i]);
        uint2 p0 = __ldg(&src[e.x * 32 + lane]);
        uint2 p1 = __ldg(&src[e.y * 32 + lane]);
        uint2 p2 = __ldg(&src[e.z * 32 + lane]);
        uint2 p3 = __ldg(&src[e.w * 32 + lane]);
        __half2 q0a = __hadd2(*(__half2*)&p0.x, *(__half2*)&p1.x);
        __half2 q0b = __hadd2(*(__half2*)&p0.y, *(__half2*)&p1.y);
        __half2 q1a = __hadd2(*(__half2*)&p2.x, *(__half2*)&p3.x);
        __half2 q1b = __hadd2(*(__half2*)&p2.y, *(__half2*)&p3.y);
        __half2 ra  = __hadd2(q0a, q1a);
        __half2 rb  = __hadd2(q0b, q1b);
        float2 f;
        f = __half22float2(ra); a0.x += f.x; a0.y += f.y;
        f = __half22float2(rb); a0.z += f.x; a0.w += f.y;
    }
    for (; i < end; i++) {
        uint2 p = __ldg(&src[__ldg(&g_adjs[i]) * 32 + lane]);
        float2 fa = __half22float2(*(__half2*)&p.x);
        float2 fb = __half22float2(*(__half2*)&p.y);
        a0.x += fa.x; a0.y += fa.y; a0.z += fb.x; a0.w += fb.y;
    }

    float di = g_dis[w];
    uint2 ps = __ldg(&src[w * 32 + lane]);
    float2 s0 = __half22float2(*(__half2*)&ps.x);
    float2 s1 = __half22float2(*(__half2*)&ps.y);
    float4 bv = __ldg(&bias4[lane]);
    float4 o;
    o.x = di * (a0.x + s0.x) + bv.x;
    o.y = di * (a0.y + s0.y) + bv.y;
    o.z = di * (a0.z + s1.x) + bv.z;
    o.w = di * (a0.w + s1.y) + bv.w;
    dst[(long)w * DV + lane] = o;
}

extern "C" void kernel_launch(void* const* d_in, const int* in_sizes, int n_in,
                              void* d_out, int out_size) {
    const float* x  = (const float*)d_in[0];
    const void*  ei = d_in[1];
    const float* W1 = (const float*)d_in[2];
    const float* b1 = (const float*)d_in[3];
    const float* W2 = (const float*)d_in[4];
    const float* b2 = (const float*)d_in[5];
    float* out = (float*)d_out;

    const int N = in_sizes[0] / D;
    const int E = in_sizes[1] / 2;

    __half*   th_ptr  = nullptr;
    __half*   th2_ptr = nullptr;
    unsigned* w1p     = nullptr;
    unsigned* w2p     = nullptr;
    cudaGetSymbolAddress((void**)&th_ptr,  g_th);
    cudaGetSymbolAddress((void**)&th2_ptr, g_th2);
    cudaGetSymbolAddress((void**)&w1p,     g_w1p);
    cudaGetSymbolAddress((void**)&w2p,     g_w2p);

    const int T = 256;
    const int eGrid    = (E + T - 1) / T;
    const int aggGrid  = (N * 32 + T - 1) / T;
    const int gemmGrid = (N + 63) / 64;

    // 4 launches: prep+scan -> gemm1+scatter -> agg1+gemm2 (tile-fused,
    // h never touches global) -> agg2.
    k_prep_scan<<<eGrid, T>>>(ei, E, N, W1, W2);                          // 1
    k_gemm_scatter<<<gemmGrid + eGrid, T>>>(x, w1p, th_ptr, N,            // 2
                                            ei, E, gemmGrid);
    k_agg_gemm<<<gemmGrid, T>>>((const uint2*)th_ptr, (const float4*)b1,  // 3
                                w2p, th2_ptr, N);
    k_agg_out<<<aggGrid, T>>>((const uint2*)th2_ptr,                      // 4
                              (const float4*)b2, (float4*)out, N);
}

// round 16
// speedup vs baseline: 1.0303x; 1.0303x over previous
#include <cuda_runtime.h>
#include <cuda_fp16.h>
#include <stdint.h>

#define D 128
#define DV 32
#define MAXN 50048
#define MAXE 1600000

// Zero-initialized at module load. Invariant: g_deg, g_cnt, g_done are zero at
// entry to kernel_launch and restored before it finishes
// (prep_scan zeroes deg + done; the final k_agg_out zeroes cnt).
__device__ int      g_deg[MAXN];
__device__ int      g_cnt[MAXN];
__device__ int      g_done;
__device__ int      g_adjs[MAXE];       // dst-sorted src ids (weights folded into t')
__device__ int      g_start[MAXN + 1];  // CSR offsets by dst
__device__ float    g_dis[MAXN];
__device__ __half   g_th[MAXN * D];     // layer-1 t' = dis*(x@W1), fp16
__device__ __half   g_hh[MAXN * D];     // hidden h = relu(...), fp16
__device__ __half   g_th2[MAXN * D];    // layer-2 t' = dis*(h@W2), fp16
__device__ unsigned g_w1p[D * D];       // W1, tf32 bits, lane-major fragment pack
__device__ unsigned g_w2p[D * D];       // W2, tf32 bits, lane-major fragment pack

__device__ __forceinline__ unsigned f2tf32(float f) {
    unsigned u;
    asm("cvt.rna.tf32.f32 %0, %1;" : "=r"(u) : "f"(f));
    return u;
}

// Lane-major fragment pack (see consumer in the GEMM):
//   word i = (((kk4*4 + wn)*4 + ks)*2 + jj)*128 + lane*4 + c
__device__ __forceinline__ void pack_w(unsigned* dst, const float* __restrict__ W, int i) {
    int c    = i & 3;
    int lane = (i >> 2) & 31;
    int jj   = (i >> 7) & 1;
    int ks   = (i >> 8) & 3;
    int wn   = (i >> 10) & 3;
    int kk4  = i >> 12;
    int j  = jj * 4 + c;
    int nt = j >> 1;
    int b  = j & 1;
    int t  = lane & 3;
    int g  = lane >> 2;
    int k = kk4 * 32 + ks * 8 + t + b * 4;
    int n = wn * 32 + nt * 8 + g;
    dst[i] = f2tf32(W[k * D + n]);
}

// ---------------------------------------------------------------------------
// Per-block dtype detect: int64 little-endian values < 2^32 -> odd 32-bit
// words all zero over 128 samples.
// ---------------------------------------------------------------------------
__device__ __forceinline__ int detect_is64(const unsigned* p, int* s_flag) {
    if (threadIdx.x == 0) *s_flag = 0;
    __syncthreads();
    if (threadIdx.x < 64) {
        unsigned nz = p[2 * threadIdx.x + 1] | p[2 * threadIdx.x + 129];
        if (nz) atomicOr(s_flag, 1);
    }
    __syncthreads();
    return *s_flag ? 0 : 1;
}

// ---------------------------------------------------------------------------
// FUSED prep + scan (last-block-done): parse edges, count degrees; first 128
// blocks pack W1/W2. Last finishing block runs the shfl exclusive scan,
// computes dis = rsqrt(deg+1), zeroes deg, resets g_done (replay-safe).
// ---------------------------------------------------------------------------
__global__ void k_prep_scan(const void* p, int E, int N,
                            const float* __restrict__ W1, const float* __restrict__ W2) {
    __shared__ int s_flag;
    __shared__ int s_last;
    int is64 = detect_is64((const unsigned*)p, &s_flag);
    int gt = blockIdx.x * blockDim.x + threadIdx.x;

    if (gt < D * D)          pack_w(g_w1p, W1, gt);
    else if (gt < 2 * D * D) pack_w(g_w2p, W2, gt - D * D);

    if (gt < E) {
        int r, c;
        if (is64) {
            const long long* q = (const long long*)p;
            r = (int)q[gt];
            c = (int)q[(long long)E + gt];
        } else {
            const int* q = (const int*)p;
            r = q[gt];
            c = q[E + gt];
        }
        atomicAdd(&g_deg[r], 1);
        atomicAdd(&g_cnt[c], 1);
    }

    __syncthreads();
    if (threadIdx.x == 0) {
        __threadfence();
        s_last = (atomicAdd(&g_done, 1) == (int)gridDim.x - 1);
    }
    __syncthreads();
    if (!s_last) return;
    __threadfence();

    __shared__ int warpBase[8];
    const int tid  = threadIdx.x;
    const int lane = tid & 31;
    const int wid  = tid >> 5;
    const int per  = (N + 255) >> 8;
    const int base = tid * per;

    int s = 0;
    {
        int i = 0;
        for (; i + 4 <= per; i += 4) {
            int i0 = base + i;
            int c0 = (i0     < N) ? g_cnt[i0]     : 0;
            int c1 = (i0 + 1 < N) ? g_cnt[i0 + 1] : 0;
            int c2 = (i0 + 2 < N) ? g_cnt[i0 + 2] : 0;
            int c3 = (i0 + 3 < N) ? g_cnt[i0 + 3] : 0;
            s += (c0 + c1) + (c2 + c3);
        }
        for (; i < per; i++) {
            int i0 = base + i;
            if (i0 < N) s += g_cnt[i0];
        }
    }

    int incl = s;
    #pragma unroll
    for (int off = 1; off < 32; off <<= 1) {
        int v = __shfl_up_sync(0xffffffffu, incl, off);
        if (lane >= off) incl += v;
    }
    if (lane == 31) warpBase[wid] = incl;
    __syncthreads();
    if (wid == 0 && lane < 8) {
        int wv = warpBase[lane];
        int wi = wv;
        #pragma unroll
        for (int off = 1; off < 8; off <<= 1) {
            int v = __shfl_up_sync(0xffu, wi, off);
            if (lane >= off) wi += v;
        }
        warpBase[lane] = wi - wv;
    }
    __syncthreads();
    int run = warpBase[wid] + (incl - s);

    {
        int i = 0;
        for (; i + 4 <= per; i += 4) {
            int i0 = base + i;
            int c0 = (i0     < N) ? g_cnt[i0]     : 0;
            int c1 = (i0 + 1 < N) ? g_cnt[i0 + 1] : 0;
            int c2 = (i0 + 2 < N) ? g_cnt[i0 + 2] : 0;
            int c3 = (i0 + 3 < N) ? g_cnt[i0 + 3] : 0;
            int d0 = (i0     < N) ? g_deg[i0]     : 0;
            int d1 = (i0 + 1 < N) ? g_deg[i0 + 1] : 0;
            int d2 = (i0 + 2 < N) ? g_deg[i0 + 2] : 0;
            int d3 = (i0 + 3 < N) ? g_deg[i0 + 3] : 0;
            if (i0 < N) {
                g_start[i0] = run;  g_cnt[i0] = 0;  g_deg[i0] = 0;
                g_dis[i0] = rsqrtf((float)(d0 + 1));
            }
            if (i0 + 1 < N) {
                g_start[i0 + 1] = run + c0;  g_cnt[i0 + 1] = 0;  g_deg[i0 + 1] = 0;
                g_dis[i0 + 1] = rsqrtf((float)(d1 + 1));
            }
            if (i0 + 2 < N) {
                g_start[i0 + 2] = run + c0 + c1;  g_cnt[i0 + 2] = 0;  g_deg[i0 + 2] = 0;
                g_dis[i0 + 2] = rsqrtf((float)(d2 + 1));
            }
            if (i0 + 3 < N) {
                g_start[i0 + 3] = run + c0 + c1 + c2;  g_cnt[i0 + 3] = 0;  g_deg[i0 + 3] = 0;
                g_dis[i0 + 3] = rsqrtf((float)(d3 + 1));
            }
            run += (c0 + c1) + (c2 + c3);
        }
        for (; i < per; i++) {
            int i0 = base + i;
            if (i0 < N) {
                int c = g_cnt[i0];
                g_start[i0] = run;  run += c;
                g_cnt[i0] = 0;
                g_dis[i0] = rsqrtf((float)(g_deg[i0] + 1));
                g_deg[i0] = 0;
            }
        }
    }
    if (tid == 0) {
        g_start[N] = E;
        g_done = 0;
    }
}

// ---------------------------------------------------------------------------
// FUSED: blocks [0, gemmBlocks) run GEMM-1 (tf32, dis[row]*(x@W1) -> g_th);
//        blocks [gemmBlocks, ...) scatter edge src ids into the adjacency.
// ---------------------------------------------------------------------------
__global__ void __launch_bounds__(256, 3)
k_gemm_scatter(const float* __restrict__ A, const unsigned* __restrict__ Wp,
               __half* __restrict__ C, int N,
               const void* p, int E, int gemmBlocks) {
    __shared__ unsigned As[64][36];

    if (blockIdx.x >= gemmBlocks) {
        int is64 = detect_is64((const unsigned*)p, (int*)&As[0][0]);
        int e = (blockIdx.x - gemmBlocks) * blockDim.x + threadIdx.x;
        if (e >= E) return;
        int r, c;
        if (is64) {
            const long long* q = (const long long*)p;
            r = (int)q[e];
            c = (int)q[(long long)E + e];
        } else {
            const int* q = (const int*)p;
            r = q[e];
            c = q[E + e];
        }
        int pos = g_start[c] + atomicAdd(&g_cnt[c], 1);
        g_adjs[pos] = r;
        return;
    }

    const int tid  = threadIdx.x;
    const int wid  = tid >> 5;
    const int lane = tid & 31;
    const int g    = lane >> 2;
    const int t    = lane & 3;
    const int wm   = wid >> 2;
    const int wn   = wid & 3;
    const int row0 = blockIdx.x * 64;

    float acc[2][4][4];
    #pragma unroll
    for (int mt = 0; mt < 2; mt++)
        #pragma unroll
        for (int nt = 0; nt < 4; nt++)
            #pragma unroll
            for (int c = 0; c < 4; c++) acc[mt][nt][c] = 0.f;

    for (int kk4 = 0; kk4 < 4; kk4++) {
        const int kk = kk4 * 32;
        #pragma unroll
        for (int it = 0; it < 2; it++) {
            int idx = tid + it * 256;
            int m  = idx >> 3;
            int k4 = idx & 7;
            float4 v = make_float4(0.f, 0.f, 0.f, 0.f);
            int gr = row0 + m;
            if (gr < N) v = *(const float4*)(A + (long)gr * D + kk + k4 * 4);
            As[m][k4 * 4 + 0] = f2tf32(v.x);
            As[m][k4 * 4 + 1] = f2tf32(v.y);
            As[m][k4 * 4 + 2] = f2tf32(v.z);
            As[m][k4 * 4 + 3] = f2tf32(v.w);
        }
        __syncthreads();

        const unsigned* wsl = Wp + ((kk4 * 4 + wn) * 4) * 256 + lane * 4;
        #pragma unroll
        for (int ks = 0; ks < 4; ks++) {
            uint4 u0 = __ldg((const uint4*)(wsl + ks * 256));
            uint4 u1 = __ldg((const uint4*)(wsl + ks * 256 + 128));
            unsigned bf[4][2] = {{u0.x, u0.y}, {u0.z, u0.w},
                                 {u1.x, u1.y}, {u1.z, u1.w}};
            #pragma unroll
            for (int mt = 0; mt < 2; mt++) {
                int mb = wm * 32 + mt * 16;
                unsigned a0 = As[mb + g    ][ks * 8 + t    ];
                unsigned a1 = As[mb + g + 8][ks * 8 + t    ];
                unsigned a2 = As[mb + g    ][ks * 8 + t + 4];
                unsigned a3 = As[mb + g + 8][ks * 8 + t + 4];
                #pragma unroll
                for (int nt = 0; nt < 4; nt++) {
                    asm volatile(
                        "mma.sync.aligned.m16n8k8.row.col.f32.tf32.tf32.f32 "
                        "{%0,%1,%2,%3}, {%4,%5,%6,%7}, {%8,%9}, {%0,%1,%2,%3};"
                        : "+f"(acc[mt][nt][0]), "+f"(acc[mt][nt][1]),
                          "+f"(acc[mt][nt][2]), "+f"(acc[mt][nt][3])
                        : "r"(a0), "r"(a1), "r"(a2), "r"(a3),
                          "r"(bf[nt][0]), "r"(bf[nt][1]));
                }
            }
        }
        __syncthreads();
    }

    #pragma unroll
    for (int mt = 0; mt < 2; mt++) {
        int r0 = row0 + wm * 32 + mt * 16 + g;
        int r1 = r0 + 8;
        float d0 = (r0 < N) ? g_dis[r0] : 0.f;
        float d1 = (r1 < N) ? g_dis[r1] : 0.f;
        #pragma unroll
        for (int nt = 0; nt < 4; nt++) {
            int n = wn * 32 + nt * 8 + 2 * t;
            if (r0 < N)
                *(__half2*)(C + (long)r0 * D + n) =
                    __floats2half2_rn(d0 * acc[mt][nt][0], d0 * acc[mt][nt][1]);
            if (r1 < N)
                *(__half2*)(C + (long)r1 * D + n) =
                    __floats2half2_rn(d1 * acc[mt][nt][2], d1 * acc[mt][nt][3]);
        }
    }
}

// ---------------------------------------------------------------------------
// Aggregation layer 1: fp16 tree sum of t1' + self, dis[dst], bias, ReLU.
// Writes h in fp16 (halves store traffic; GEMM-2 reads fp16).
// ---------------------------------------------------------------------------
__global__ void __launch_bounds__(256)
k_agg_h(const uint2* __restrict__ src, const float4* __restrict__ bias4,
        uint2* __restrict__ dst, int N) {
    int w = (blockIdx.x * blockDim.x + threadIdx.x) >> 5;
    if (w >= N) return;
    const int lane = threadIdx.x & 31;
    int i = g_start[w];
    const int end = g_start[w + 1];

    float4 a0 = make_float4(0.f, 0.f, 0.f, 0.f);

    while ((i & 3) && i < end) {
        uint2 p = __ldg(&src[__ldg(&g_adjs[i]) * 32 + lane]);
        float2 fa = __half22float2(*(__half2*)&p.x);
        float2 fb = __half22float2(*(__half2*)&p.y);
        a0.x += fa.x; a0.y += fa.y; a0.z += fb.x; a0.w += fb.y;
        i++;
    }
    for (; i + 4 <= end; i += 4) {
        int4 e = __ldg((const int4*)&g_adjs[i]);
        uint2 p0 = __ldg(&src[e.x * 32 + lane]);
        uint2 p1 = __ldg(&src[e.y * 32 + lane]);
        uint2 p2 = __ldg(&src[e.z * 32 + lane]);
        uint2 p3 = __ldg(&src[e.w * 32 + lane]);
        __half2 q0a = __hadd2(*(__half2*)&p0.x, *(__half2*)&p1.x);
        __half2 q0b = __hadd2(*(__half2*)&p0.y, *(__half2*)&p1.y);
        __half2 q1a = __hadd2(*(__half2*)&p2.x, *(__half2*)&p3.x);
        __half2 q1b = __hadd2(*(__half2*)&p2.y, *(__half2*)&p3.y);
        __half2 ra  = __hadd2(q0a, q1a);
        __half2 rb  = __hadd2(q0b, q1b);
        float2 f;
        f = __half22float2(ra); a0.x += f.x; a0.y += f.y;
        f = __half22float2(rb); a0.z += f.x; a0.w += f.y;
    }
    for (; i < end; i++) {
        uint2 p = __ldg(&src[__ldg(&g_adjs[i]) * 32 + lane]);
        float2 fa = __half22float2(*(__half2*)&p.x);
        float2 fb = __half22float2(*(__half2*)&p.y);
        a0.x += fa.x; a0.y += fa.y; a0.z += fb.x; a0.w += fb.y;
    }

    float di = g_dis[w];
    uint2 ps = __ldg(&src[w * 32 + lane]);
    float2 s0 = __half22float2(*(__half2*)&ps.x);
    float2 s1 = __half22float2(*(__half2*)&ps.y);
    float4 bv = __ldg(&bias4[lane]);
    float ox = fmaxf(di * (a0.x + s0.x) + bv.x, 0.f);
    float oy = fmaxf(di * (a0.y + s0.y) + bv.y, 0.f);
    float oz = fmaxf(di * (a0.z + s1.x) + bv.z, 0.f);
    float ow = fmaxf(di * (a0.w + s1.y) + bv.w, 0.f);
    uint2 r;
    *(__half2*)&r.x = __floats2half2_rn(ox, oy);
    *(__half2*)&r.y = __floats2half2_rn(oz, ow);
    dst[(long)w * 32 + lane] = r;
}

// ---------------------------------------------------------------------------
// GEMM layer 2: A in fp16 (h), staging converts half2->float2->tf32; same
// coalescing (8B/lane -> 256B/warp), identical mma loop. Output dis-scaled
// fp16.
// ---------------------------------------------------------------------------
__global__ void __launch_bounds__(256, 3)
k_gemm_tf32h(const __half* __restrict__ A, const unsigned* __restrict__ Wp,
             __half* __restrict__ C, int N) {
    __shared__ unsigned As[64][36];

    const int tid  = threadIdx.x;
    const int wid  = tid >> 5;
    const int lane = tid & 31;
    const int g    = lane >> 2;
    const int t    = lane & 3;
    const int wm   = wid >> 2;
    const int wn   = wid & 3;
    const int row0 = blockIdx.x * 64;

    float acc[2][4][4];
    #pragma unroll
    for (int mt = 0; mt < 2; mt++)
        #pragma unroll
        for (int nt = 0; nt < 4; nt++)
            #pragma unroll
            for (int c = 0; c < 4; c++) acc[mt][nt][c] = 0.f;

    for (int kk4 = 0; kk4 < 4; kk4++) {
        const int kk = kk4 * 32;
        #pragma unroll
        for (int it = 0; it < 2; it++) {
            int idx = tid + it * 256;
            int m  = idx >> 3;
            int k4 = idx & 7;
            uint2 v = make_uint2(0u, 0u);
            int gr = row0 + m;
            if (gr < N) v = *(const uint2*)(A + (long)gr * D + kk + k4 * 4);
            float2 f0 = __half22float2(*(__half2*)&v.x);
            float2 f1 = __half22float2(*(__half2*)&v.y);
            As[m][k4 * 4 + 0] = f2tf32(f0.x);
            As[m][k4 * 4 + 1] = f2tf32(f0.y);
            As[m][k4 * 4 + 2] = f2tf32(f1.x);
            As[m][k4 * 4 + 3] = f2tf32(f1.y);
        }
        __syncthreads();

        const unsigned* wsl = Wp + ((kk4 * 4 + wn) * 4) * 256 + lane * 4;
        #pragma unroll
        for (int ks = 0; ks < 4; ks++) {
            uint4 u0 = __ldg((const uint4*)(wsl + ks * 256));
            uint4 u1 = __ldg((const uint4*)(wsl + ks * 256 + 128));
            unsigned bf[4][2] = {{u0.x, u0.y}, {u0.z, u0.w},
                                 {u1.x, u1.y}, {u1.z, u1.w}};
            #pragma unroll
            for (int mt = 0; mt < 2; mt++) {
                int mb = wm * 32 + mt * 16;
                unsigned a0 = As[mb + g    ][ks * 8 + t    ];
                unsigned a1 = As[mb + g + 8][ks * 8 + t    ];
                unsigned a2 = As[mb + g    ][ks * 8 + t + 4];
                unsigned a3 = As[mb + g + 8][ks * 8 + t + 4];
                #pragma unroll
                for (int nt = 0; nt < 4; nt++) {
                    asm volatile(
                        "mma.sync.aligned.m16n8k8.row.col.f32.tf32.tf32.f32 "
                        "{%0,%1,%2,%3}, {%4,%5,%6,%7}, {%8,%9}, {%0,%1,%2,%3};"
                        : "+f"(acc[mt][nt][0]), "+f"(acc[mt][nt][1]),
                          "+f"(acc[mt][nt][2]), "+f"(acc[mt][nt][3])
                        : "r"(a0), "r"(a1), "r"(a2), "r"(a3),
                          "r"(bf[nt][0]), "r"(bf[nt][1]));
                }
            }
        }
        __syncthreads();
    }

    #pragma unroll
    for (int mt = 0; mt < 2; mt++) {
        int r0 = row0 + wm * 32 + mt * 16 + g;
        int r1 = r0 + 8;
        float d0 = (r0 < N) ? g_dis[r0] : 0.f;
        float d1 = (r1 < N) ? g_dis[r1] : 0.f;
        #pragma unroll
        for (int nt = 0; nt < 4; nt++) {
            int n = wn * 32 + nt * 8 + 2 * t;
            if (r0 < N)
                *(__half2*)(C + (long)r0 * D + n) =
                    __floats2half2_rn(d0 * acc[mt][nt][0], d0 * acc[mt][nt][1]);
            if (r1 < N)
                *(__half2*)(C + (long)r1 * D + n) =
                    __floats2half2_rn(d1 * acc[mt][nt][2], d1 * acc[mt][nt][3]);
        }
    }
}

// ---------------------------------------------------------------------------
// Final aggregation (layer 2): fp16 tree sum + bias, fp32 out; zeroes g_cnt.
// ---------------------------------------------------------------------------
__global__ void __launch_bounds__(256)
k_agg_out(const uint2* __restrict__ src, const float4* __restrict__ bias4,
          float4* __restrict__ dst, int N) {
    int idx = blockIdx.x * blockDim.x + threadIdx.x;
    if (idx < MAXN) g_cnt[idx] = 0;   // restore invariant
    int w = idx >> 5;
    if (w >= N) return;
    const int lane = threadIdx.x & 31;
    int i = g_start[w];
    const int end = g_start[w + 1];

    float4 a0 = make_float4(0.f, 0.f, 0.f, 0.f);

    while ((i & 3) && i < end) {
        uint2 p = __ldg(&src[__ldg(&g_adjs[i]) * 32 + lane]);
        float2 fa = __half22float2(*(__half2*)&p.x);
        float2 fb = __half22float2(*(__half2*)&p.y);
        a0.x += fa.x; a0.y += fa.y; a0.z += fb.x; a0.w += fb.y;
        i++;
    }
    for (; i + 4 <= end; i += 4) {
        int4 e = __ldg((const int4*)&g_adjs[i]);
        uint2 p0 = __ldg(&src[e.x * 32 + lane]);
        uint2 p1 = __ldg(&src[e.y * 32 + lane]);
        uint2 p2 = __ldg(&src[e.z * 32 + lane]);
        uint2 p3 = __ldg(&src[e.w * 32 + lane]);
        __half2 q0a = __hadd2(*(__half2*)&p0.x, *(__half2*)&p1.x);
        __half2 q0b = __hadd2(*(__half2*)&p0.y, *(__half2*)&p1.y);
        __half2 q1a = __hadd2(*(__half2*)&p2.x, *(__half2*)&p3.x);
        __half2 q1b = __hadd2(*(__half2*)&p2.y, *(__half2*)&p3.y);
        __half2 ra  = __hadd2(q0a, q1a);
        __half2 rb  = __hadd2(q0b, q1b);
        float2 f;
        f = __half22float2(ra); a0.x += f.x; a0.y += f.y;
        f = __half22float2(rb); a0.z += f.x; a0.w += f.y;
    }
    for (; i < end; i++) {
        uint2 p = __ldg(&src[__ldg(&g_adjs[i]) * 32 + lane]);
        float2 fa = __half22float2(*(__half2*)&p.x);
        float2 fb = __half22float2(*(__half2*)&p.y);
        a0.x += fa.x; a0.y += fa.y; a0.z += fb.x; a0.w += fb.y;
    }

    float di = g_dis[w];
    uint2 ps = __ldg(&src[w * 32 + lane]);
    float2 s0 = __half22float2(*(__half2*)&ps.x);
    float2 s1 = __half22float2(*(__half2*)&ps.y);
    float4 bv = __ldg(&bias4[lane]);
    float4 o;
    o.x = di * (a0.x + s0.x) + bv.x;
    o.y = di * (a0.y + s0.y) + bv.y;
    o.z = di * (a0.z + s1.x) + bv.z;
    o.w = di * (a0.w + s1.y) + bv.w;
    dst[(long)w * DV + lane] = o;
}

extern "C" void kernel_launch(void* const* d_in, const int* in_sizes, int n_in,
                              void* d_out, int out_size) {
    const float* x  = (const float*)d_in[0];
    const void*  ei = d_in[1];
    const float* W1 = (const float*)d_in[2];
    const float* b1 = (const float*)d_in[3];
    const float* W2 = (const float*)d_in[4];
    const float* b2 = (const float*)d_in[5];
    float* out = (float*)d_out;

    const int N = in_sizes[0] / D;
    const int E = in_sizes[1] / 2;

    __half*   th_ptr  = nullptr;
    __half*   hh_ptr  = nullptr;
    __half*   th2_ptr = nullptr;
    unsigned* w1p     = nullptr;
    unsigned* w2p     = nullptr;
    cudaGetSymbolAddress((void**)&th_ptr,  g_th);
    cudaGetSymbolAddress((void**)&hh_ptr,  g_hh);
    cudaGetSymbolAddress((void**)&th2_ptr, g_th2);
    cudaGetSymbolAddress((void**)&w1p,     g_w1p);
    cudaGetSymbolAddress((void**)&w2p,     g_w2p);

    const int T = 256;
    const int eGrid    = (E + T - 1) / T;
    const int aggGrid  = (N * 32 + T - 1) / T;
    const int gemmGrid = (N + 63) / 64;

    // Round-14 champion structure; h stored fp16 (halved h traffic).
    k_prep_scan<<<eGrid, T>>>(ei, E, N, W1, W2);                          // 1
    k_gemm_scatter<<<gemmGrid + eGrid, T>>>(x, w1p, th_ptr, N,            // 2
                                            ei, E, gemmGrid);
    k_agg_h<<<aggGrid, T>>>((const uint2*)th_ptr, (const float4*)b1,      // 3
                            (uint2*)hh_ptr, N);
    k_gemm_tf32h<<<gemmGrid, T>>>(hh_ptr, w2p, th2_ptr, N);               // 4
    k_agg_out<<<aggGrid, T>>>((const uint2*)th2_ptr,                      // 5
                              (const float4*)b2, (float4*)out, N);
}